// round 14
// baseline (speedup 1.0000x reference)
#include <cuda_runtime.h>
#include <cuda_fp16.h>
#include <mma.h>
#include <math.h>
#include <stdint.h>

using namespace nvcuda;

#define TOK  2048
#define HDIM 2048
#define FDIM 7168
#define NEXP 8
#define TOPK 2

#define BM 128
#define BK 64
#define NC1 (HDIM / BK)   // 32
#define NC2 (FDIM / BK)   // 112

#define BN1 128
#define BN2 256
#define NB1 (FDIM / BN1)  // 56 gemm1 N-tiles
#define W2SL 7            // extra blockIdx.y slices in gemm1 grid for w2 conversion

#define ALDH 72           // A smem row stride (halves): 64 data + 8 pad
#define BLDH1 136         // gemm1 B stride: 128 + 8
#define BLDH2 264         // gemm2 B stride: 256 + 8
#define CLD1 136
#define CLD2 264

#define ASZH  (BM * ALDH)           // 9216 halves
#define BSZH1 (BK * BLDH1)          // 8704 halves
#define BSZH2 (BK * BLDH2)          // 16896 halves
#define STG1H (ASZH + 2 * BSZH1)    // 26624 halves = 53248 B
#define STG2H (ASZH + BSZH2)        // 26112 halves = 52224 B
#define DYN1 (3 * STG1H * 2)        // 159744 B (3-stage)
#define DYN2 (4 * STG2H * 2)        // 208896 B (4-stage)

// ---------------- scratch ----------------
__device__ int    g_cnt[NEXP];
__device__ int    g_tok[NEXP * TOK];
__device__ int    g_dst[NEXP * TOK];
__device__ float  g_wt [NEXP * TOK];
__device__ __half g_xh  [(size_t)TOK * HDIM];
__device__ __half g_w1h [(size_t)NEXP * HDIM * FDIM];
__device__ __half g_w3h [(size_t)NEXP * HDIM * FDIM];
__device__ __half g_w2h [(size_t)NEXP * FDIM * HDIM];
__device__ __half g_hidh[(size_t)NEXP * TOK * FDIM];
__device__ float  g_partial[(size_t)TOK * TOPK * HDIM];

// ---------------- helpers ----------------
__device__ __forceinline__ uint32_t smem_u32(const void* p) {
    uint32_t a;
    asm("{ .reg .u64 t; cvta.to.shared.u64 t, %1; cvt.u32.u64 %0, t; }" : "=r"(a) : "l"(p));
    return a;
}
__device__ __forceinline__ void cpa(uint32_t s, const void* g) {
    asm volatile("cp.async.cg.shared.global [%0], [%1], 16;" :: "r"(s), "l"(g));
}
__device__ __forceinline__ void cpcommit() { asm volatile("cp.async.commit_group;"); }
template <int N>
__device__ __forceinline__ void cpwait() { asm volatile("cp.async.wait_group %0;" :: "n"(N)); }

__device__ __forceinline__ void f2h_chunk(const float* __restrict__ s,
                                          __half* __restrict__ d, size_t i) {
    float4 a = *(const float4*)(s + i);
    float4 b = *(const float4*)(s + i + 4);
    __half2 h0 = __floats2half2_rn(a.x, a.y);
    __half2 h1 = __floats2half2_rn(a.z, a.w);
    __half2 h2 = __floats2half2_rn(b.x, b.y);
    __half2 h3 = __floats2half2_rn(b.z, b.w);
    uint4 o;
    o.x = *(uint32_t*)&h0; o.y = *(uint32_t*)&h1;
    o.z = *(uint32_t*)&h2; o.w = *(uint32_t*)&h3;
    *(uint4*)(d + i) = o;
}

// ---------------- prep: route + f2h(x) + f2h(w1) + f2h(w3), one fused grid ----------------
// grid.x = 2048 (route) + 2048 (x) + 57344 (w1) + 57344 (w3) = 118784, 256 threads
__global__ void prep_kernel(const float* __restrict__ x, const float* __restrict__ gw,
                            const float* __restrict__ w1, const float* __restrict__ w3,
                            __half* __restrict__ xh, __half* __restrict__ w1h,
                            __half* __restrict__ w3h) {
    const int bid = blockIdx.x;
    const int tid = threadIdx.x;

    if (bid >= 2048) {
        int cb = bid - 2048;
        if (cb < 2048) {
            f2h_chunk(x, xh, ((size_t)cb * 256 + tid) * 8);
        } else if (cb < 2048 + 57344) {
            f2h_chunk(w1, w1h, ((size_t)(cb - 2048) * 256 + tid) * 8);
        } else {
            f2h_chunk(w3, w3h, ((size_t)(cb - 2048 - 57344) * 256 + tid) * 8);
        }
        return;
    }

    // ---- routing: fp32 gate, exact top-2 (strict > keeps lowest index on ties) ----
    const int t = bid;
    float acc[NEXP];
#pragma unroll
    for (int e = 0; e < NEXP; e++) acc[e] = 0.f;

    const float* xt = x + (size_t)t * HDIM;
    for (int h = tid; h < HDIM; h += 256) {
        float xv = xt[h];
#pragma unroll
        for (int e = 0; e < NEXP; e++) acc[e] += xv * gw[h * NEXP + e];
    }

    __shared__ float s[NEXP][256];
#pragma unroll
    for (int e = 0; e < NEXP; e++) s[e][tid] = acc[e];
    __syncthreads();
    for (int off = 128; off > 0; off >>= 1) {
        if (tid < off) {
#pragma unroll
            for (int e = 0; e < NEXP; e++) s[e][tid] += s[e][tid + off];
        }
        __syncthreads();
    }

    if (tid == 0) {
        float v[NEXP];
#pragma unroll
        for (int e = 0; e < NEXP; e++) v[e] = s[e][0];
        int i1 = 0;
#pragma unroll
        for (int e = 1; e < NEXP; e++) if (v[e] > v[i1]) i1 = e;
        int i2 = (i1 == 0) ? 1 : 0;
#pragma unroll
        for (int e = 0; e < NEXP; e++)
            if (e != i1 && v[e] > v[i2]) i2 = e;

        float m  = fmaxf(v[i1], v[i2]);
        float e1 = __expf(v[i1] - m);
        float e2 = __expf(v[i2] - m);
        float inv = 1.f / (e1 + e2);

        int s0 = atomicAdd(&g_cnt[i1], 1);
        g_tok[i1 * TOK + s0] = t;
        g_dst[i1 * TOK + s0] = t * TOPK + 0;
        g_wt [i1 * TOK + s0] = e1 * inv;
        int s1 = atomicAdd(&g_cnt[i2], 1);
        g_tok[i2 * TOK + s1] = t;
        g_dst[i2 * TOK + s1] = t * TOPK + 1;
        g_wt [i2 * TOK + s1] = e2 * inv;
    }
}

// ---------------- GEMM1 (+ fused f2h(w2) on extra y-slices) ----------------
// grid = (16, NB1 + W2SL, 8); y >= NB1 -> w2 conversion block
__global__ __launch_bounds__(256)
void gemm1_kernel(const float* __restrict__ w2, __half* __restrict__ w2h) {
    extern __shared__ __half sm[];

    if (blockIdx.y >= NB1) {
        // f2h(w2): 896 blocks x 64 iters x 2048 halves = NEXP*FDIM*HDIM
        const int fid = (blockIdx.z * W2SL + (blockIdx.y - NB1)) * 16 + blockIdx.x;
        const size_t base = (size_t)fid * 131072;
#pragma unroll 4
        for (int it = 0; it < 64; it++)
            f2h_chunk(w2, w2h, base + (size_t)it * 2048 + threadIdx.x * 8);
        return;
    }

    const int ex  = blockIdx.z;
    const int n_e = g_cnt[ex];
    const int m0  = blockIdx.x * BM;
    if (m0 >= n_e) return;
    const int n0  = blockIdx.y * BN1;
    const int tid = threadIdx.x;
    const int wid = tid >> 5;
    const int wm  = wid & 1, wn = wid >> 1;

    const uint32_t smb = smem_u32(sm);

    // A loader: 2 threads/row, 4 chunks (16B) each; row ar, halves [acb*8, acb*8+32)
    const int ar = tid >> 1, acb = (tid & 1) * 4;
    int rc = m0 + ar; if (rc > n_e - 1) rc = n_e - 1;
    const __half* asrc = g_xh + (size_t)g_tok[ex * TOK + rc] * HDIM + acb * 8;
    const uint32_t aoff = (ar * ALDH + acb * 8) * 2;

    // B loaders: 4 threads/k-row, 4 chunks each; k-row rb, halves [bcb*8, bcb*8+32)
    const int rb = tid >> 2, bcb = (tid & 3) * 4;
    const __half* b1src = g_w1h + (size_t)ex * HDIM * FDIM + (size_t)rb * FDIM + n0 + bcb * 8;
    const __half* b3src = g_w3h + (size_t)ex * HDIM * FDIM + (size_t)rb * FDIM + n0 + bcb * 8;
    const uint32_t boff = (rb * BLDH1 + bcb * 8) * 2;

    auto issue = [&](int c) {
        const uint32_t base = smb + (uint32_t)(c % 3) * (STG1H * 2);
        const int k0 = c * BK;
        const __half* sa = asrc + k0;
        const uint32_t ab = base + aoff;
#pragma unroll
        for (int u = 0; u < 4; u++) cpa(ab + u * 16, sa + u * 8);
        const __half* s1 = b1src + (size_t)k0 * FDIM;
        const __half* s3 = b3src + (size_t)k0 * FDIM;
        const uint32_t b1b = base + ASZH * 2 + boff;
        const uint32_t b3b = base + (ASZH + BSZH1) * 2 + boff;
#pragma unroll
        for (int u = 0; u < 4; u++) cpa(b1b + u * 16, s1 + u * 8);
#pragma unroll
        for (int u = 0; u < 4; u++) cpa(b3b + u * 16, s3 + u * 8);
        cpcommit();
    };

    wmma::fragment<wmma::accumulator, 16, 16, 16, float> acc1[4][2], acc3[4][2];
#pragma unroll
    for (int i = 0; i < 4; i++)
#pragma unroll
        for (int j = 0; j < 2; j++) {
            wmma::fill_fragment(acc1[i][j], 0.f);
            wmma::fill_fragment(acc3[i][j], 0.f);
        }

    issue(0); issue(1);
    for (int c = 0; c < NC1; c++) {
        if (c + 1 < NC1) cpwait<1>();
        else cpwait<0>();
        __syncthreads();
        if (c + 2 < NC1) issue(c + 2);   // writes stage (c-1)%3, consumed at iter c-1

        const __half* As  = sm + (c % 3) * STG1H;
        const __half* B1s = As + ASZH;
        const __half* B3s = As + ASZH + BSZH1;
#pragma unroll
        for (int kc = 0; kc < BK; kc += 16) {
            wmma::fragment<wmma::matrix_a, 16, 16, 16, __half, wmma::row_major> af[4];
            wmma::fragment<wmma::matrix_b, 16, 16, 16, __half, wmma::row_major> bf1[2], bf3[2];
#pragma unroll
            for (int i = 0; i < 4; i++)
                wmma::load_matrix_sync(af[i], As + (wm * 64 + i * 16) * ALDH + kc, ALDH);
#pragma unroll
            for (int j = 0; j < 2; j++) {
                wmma::load_matrix_sync(bf1[j], B1s + kc * BLDH1 + wn * 32 + j * 16, BLDH1);
                wmma::load_matrix_sync(bf3[j], B3s + kc * BLDH1 + wn * 32 + j * 16, BLDH1);
            }
#pragma unroll
            for (int i = 0; i < 4; i++)
#pragma unroll
                for (int j = 0; j < 2; j++) {
                    wmma::mma_sync(acc1[i][j], af[i], bf1[j], acc1[i][j]);
                    wmma::mma_sync(acc3[i][j], af[i], bf3[j], acc3[i][j]);
                }
        }
    }
    __syncthreads();

    // epilogue: silu(h1)*h3, two 64-row phases through smem, fp16 global store
    float* Cs = (float*)sm;
    __half* hidb = g_hidh + (size_t)ex * TOK * FDIM;
#pragma unroll 1
    for (int p = 0; p < 2; p++) {
        if (wm == p) {
#pragma unroll
            for (int i = 0; i < 4; i++)
#pragma unroll
                for (int j = 0; j < 2; j++) {
#pragma unroll
                    for (int t = 0; t < acc1[i][j].num_elements; t++) {
                        float h1 = acc1[i][j].x[t];
                        float h3 = acc3[i][j].x[t];
                        acc1[i][j].x[t] = (h1 / (1.f + __expf(-h1))) * h3;
                    }
                    wmma::store_matrix_sync(Cs + (i * 16) * CLD1 + wn * 32 + j * 16,
                                            acc1[i][j], CLD1, wmma::mem_row_major);
                }
        }
        __syncthreads();
#pragma unroll
        for (int it = 0; it < 4; it++) {
            int u = tid + 256 * it;
            int r = u >> 4, c8 = u & 15;
            int grow = m0 + p * 64 + r;
            if (grow < n_e) {
                const float* src = Cs + r * CLD1 + c8 * 8;
                __half2 h0 = __floats2half2_rn(src[0], src[1]);
                __half2 h1 = __floats2half2_rn(src[2], src[3]);
                __half2 h2 = __floats2half2_rn(src[4], src[5]);
                __half2 h3 = __floats2half2_rn(src[6], src[7]);
                uint4 o;
                o.x = *(uint32_t*)&h0; o.y = *(uint32_t*)&h1;
                o.z = *(uint32_t*)&h2; o.w = *(uint32_t*)&h3;
                *(uint4*)(hidb + (size_t)grow * FDIM + n0 + c8 * 8) = o;
            }
        }
        __syncthreads();
    }
}

// ---------------- GEMM2: partial = (hid @ W2) * combine_wt; 512 thr, 128x256, BK=64, 4-stage ----------------
__global__ __launch_bounds__(512)
void gemm2_kernel() {
    extern __shared__ __half sm[];
    const int ex  = blockIdx.z;
    const int n_e = g_cnt[ex];
    const int m0  = blockIdx.x * BM;
    if (m0 >= n_e) return;
    const int n0  = blockIdx.y * BN2;
    const int tid = threadIdx.x;
    const int wid = tid >> 5;
    const int wm  = wid & 1, wn = wid >> 1;

    const uint32_t smb = smem_u32(sm);

    // A loader: 4 threads/row, 2 chunks each; halves [ac2*8, ac2*8+16)
    const int ar = tid >> 2, ac2 = (tid & 3) * 2;
    int rc = m0 + ar; if (rc > n_e - 1) rc = n_e - 1;
    const __half* asrc = g_hidh + ((size_t)ex * TOK + rc) * FDIM + ac2 * 8;
    const uint32_t aoff = (ar * ALDH + ac2 * 8) * 2;

    // B loader: 8 threads/k-row, 4 chunks each; halves [bc*8, bc*8+32)
    const int rb = tid >> 3, bc = (tid & 7) * 4;
    const __half* bsrc = g_w2h + (size_t)ex * FDIM * HDIM + (size_t)rb * HDIM + n0 + bc * 8;
    const uint32_t boff = (rb * BLDH2 + bc * 8) * 2;

    auto issue = [&](int c) {
        const uint32_t base = smb + (uint32_t)(c & 3) * (STG2H * 2);
        const int k0 = c * BK;
        const __half* sa = asrc + k0;
        const uint32_t ab = base + aoff;
        cpa(ab, sa); cpa(ab + 16, sa + 8);
        const __half* s2 = bsrc + (size_t)k0 * HDIM;
        const uint32_t bb = base + ASZH * 2 + boff;
#pragma unroll
        for (int u = 0; u < 4; u++) cpa(bb + u * 16, s2 + u * 8);
        cpcommit();
    };

    wmma::fragment<wmma::accumulator, 16, 16, 16, float> acc[4][2];
#pragma unroll
    for (int i = 0; i < 4; i++)
#pragma unroll
        for (int j = 0; j < 2; j++) wmma::fill_fragment(acc[i][j], 0.f);

    issue(0); issue(1); issue(2);
    for (int c = 0; c < NC2; c++) {
        if (c + 2 < NC2) cpwait<2>();
        else if (c + 1 < NC2) cpwait<1>();
        else cpwait<0>();
        __syncthreads();
        if (c + 3 < NC2) issue(c + 3);   // writes stage (c-1)&3, consumed at iter c-1

        const __half* As = sm + (c & 3) * STG2H;
        const __half* Bs = As + ASZH;
#pragma unroll
        for (int kc = 0; kc < BK; kc += 16) {
            wmma::fragment<wmma::matrix_a, 16, 16, 16, __half, wmma::row_major> af[4];
            wmma::fragment<wmma::matrix_b, 16, 16, 16, __half, wmma::row_major> bf[2];
#pragma unroll
            for (int i = 0; i < 4; i++)
                wmma::load_matrix_sync(af[i], As + (wm * 64 + i * 16) * ALDH + kc, ALDH);
#pragma unroll
            for (int j = 0; j < 2; j++)
                wmma::load_matrix_sync(bf[j], Bs + kc * BLDH2 + wn * 32 + j * 16, BLDH2);
#pragma unroll
            for (int i = 0; i < 4; i++)
#pragma unroll
                for (int j = 0; j < 2; j++)
                    wmma::mma_sync(acc[i][j], af[i], bf[j], acc[i][j]);
        }
    }
    __syncthreads();

    float* Cs = (float*)sm;
#pragma unroll 1
    for (int p = 0; p < 2; p++) {
        if (wm == p) {
#pragma unroll
            for (int i = 0; i < 4; i++)
#pragma unroll
                for (int j = 0; j < 2; j++)
                    wmma::store_matrix_sync(Cs + (i * 16) * CLD2 + wn * 32 + j * 16,
                                            acc[i][j], CLD2, wmma::mem_row_major);
        }
        __syncthreads();
#pragma unroll
        for (int it = 0; it < 8; it++) {
            int u = tid + 512 * it;
            int r = u >> 6, c4 = u & 63;
            int grow = m0 + p * 64 + r;
            if (grow < n_e) {
                int   drow = g_dst[ex * TOK + grow];
                float w    = g_wt [ex * TOK + grow];
                const float* src = Cs + r * CLD2 + c4 * 4;
                float4 v;
                v.x = w * src[0]; v.y = w * src[1];
                v.z = w * src[2]; v.w = w * src[3];
                *(float4*)(g_partial + (size_t)drow * HDIM + n0 + c4 * 4) = v;
            }
        }
        __syncthreads();
    }
}

__global__ void combine_kernel(float* __restrict__ out) {
    const size_t i = (size_t)blockIdx.x * 256 + threadIdx.x;
    const int c = HDIM / 4;
    const size_t t = i / c;
    const size_t j = i % c;
    const float4* p = (const float4*)g_partial;
    float4 a = p[(t * 2 + 0) * c + j];
    float4 b = p[(t * 2 + 1) * c + j];
    float4 r;
    r.x = a.x + b.x; r.y = a.y + b.y; r.z = a.z + b.z; r.w = a.w + b.w;
    ((float4*)out)[i] = r;
}

// ---------------- launch ----------------
extern "C" void kernel_launch(void* const* d_in, const int* in_sizes, int n_in,
                              void* d_out, int out_size) {
    const float* x  = (const float*)d_in[0];
    const float* gw = (const float*)d_in[1];
    const float* w1 = (const float*)d_in[2];
    const float* w3 = (const float*)d_in[3];
    const float* w2 = (const float*)d_in[4];
    float* out = (float*)d_out;

    cudaFuncSetAttribute(gemm1_kernel, cudaFuncAttributeMaxDynamicSharedMemorySize, DYN1);
    cudaFuncSetAttribute(gemm2_kernel, cudaFuncAttributeMaxDynamicSharedMemorySize, DYN2);

    __half* xh;  cudaGetSymbolAddress((void**)&xh,  g_xh);
    __half* w1h; cudaGetSymbolAddress((void**)&w1h, g_w1h);
    __half* w3h; cudaGetSymbolAddress((void**)&w3h, g_w3h);
    __half* w2h; cudaGetSymbolAddress((void**)&w2h, g_w2h);
    int* cnt;    cudaGetSymbolAddress((void**)&cnt, g_cnt);

    cudaMemsetAsync(cnt, 0, NEXP * sizeof(int));

    // fused prep: route (2048) + f2h x (2048) + f2h w1 (57344) + f2h w3 (57344)
    prep_kernel<<<118784, 256>>>(x, gw, w1, w3, xh, w1h, w3h);

    // gemm1 with fused f2h(w2) slices
    dim3 g1(TOK / BM, NB1 + W2SL, NEXP);
    gemm1_kernel<<<g1, 256, DYN1>>>(w2, w2h);

    dim3 g2(TOK / BM, HDIM / BN2, NEXP);
    gemm2_kernel<<<g2, 512, DYN2>>>();

    combine_kernel<<<(TOK * HDIM / 4) / 256, 256>>>(out);
}